// round 14
// baseline (speedup 1.0000x reference)
#include <cuda_runtime.h>
#include <cuda_bf16.h>
#include <cstdint>

static constexpr int Sc = 2048, Dc = 64;

// fragment buffers:
// Q: ((bh*128+blk)*2+sp)*4+ks -> [lane] uint4(a0,a1,a2,a3)
// K: ((bh*256+cbg)*2+sp)*2+kp -> [lane] uint4(ks_even b0,b1, ks_odd b0,b1)
__device__ uint4 g_qfrag[64 * 128 * 2 * 4 * 32];
__device__ uint4 g_kfrag[64 * 256 * 2 * 2 * 32];

__device__ __forceinline__ void threefry2x32(uint32_t c0, uint32_t c1,
                                             uint32_t& o0, uint32_t& o1)
{
    const uint32_t K0 = 0u, K1 = 42u, K2 = 0x1BD11BDAu ^ K0 ^ K1;
    uint32_t x0 = c0 + K0, x1 = c1 + K1;
#define TF_R(r) { x0 += x1; x1 = __funnelshift_l(x1, x1, (r)); x1 ^= x0; }
    TF_R(13) TF_R(15) TF_R(26) TF_R(6)  x0 += K1; x1 += K2 + 1u;
    TF_R(17) TF_R(29) TF_R(16) TF_R(24) x0 += K2; x1 += K0 + 2u;
    TF_R(13) TF_R(15) TF_R(26) TF_R(6)  x0 += K0; x1 += K1 + 3u;
    TF_R(17) TF_R(29) TF_R(16) TF_R(24) x0 += K1; x1 += K2 + 4u;
    TF_R(13) TF_R(15) TF_R(26) TF_R(6)  x0 += K2; x1 += K0 + 5u;
#undef TF_R
    o0 = x0; o1 = x1;
}
__device__ __forceinline__ bool keep_mask(uint32_t bh, uint32_t gq, uint32_t gk)
{
    uint32_t i = (bh << 22) | (gq << 11) | gk, b0, b1;
    threefry2x32(0u, i, b0, b1);
    return ((b0 ^ b1) >> 9) < 838861u;
}

__device__ __forceinline__ uint32_t pk_bf16(float lo, float hi)
{ uint32_t r; asm("cvt.rn.bf16x2.f32 %0, %1, %2;" : "=r"(r) : "f"(hi), "f"(lo)); return r; }

__device__ __forceinline__ uint32_t pk_split(float x, float y, int sp)
{
    float xh = __bfloat162float(__float2bfloat16(x));
    float yh = __bfloat162float(__float2bfloat16(y));
    return sp ? pk_bf16(x - xh, y - yh) : pk_bf16(xh, yh);
}

// order-preserving float->uint key
__device__ __forceinline__ uint32_t okey(float f)
{
    uint32_t u = __float_as_uint(f);
    return (u & 0x80000000u) ? ~u : (u | 0x80000000u);
}

__device__ __forceinline__ void mma16816(float& c0, float& c1, float& c2, float& c3,
                                         uint32_t a0, uint32_t a1, uint32_t a2, uint32_t a3,
                                         uint32_t b0, uint32_t b1)
{
    asm volatile("mma.sync.aligned.m16n8k16.row.col.f32.bf16.bf16.f32 "
                 "{%0,%1,%2,%3}, {%4,%5,%6,%7}, {%8,%9}, {%0,%1,%2,%3};"
                 : "+f"(c0), "+f"(c1), "+f"(c2), "+f"(c3)
                 : "r"(a0), "r"(a1), "r"(a2), "r"(a3), "r"(b0), "r"(b1));
}

// ---------------- pre-pass (unchanged) ---------------------------------------
__global__ void __launch_bounds__(256)
prepass_kernel(const float* __restrict__ q, const float* __restrict__ k)
{
    int gw = (blockIdx.x * 256 + threadIdx.x) >> 5;
    int lane = threadIdx.x & 31;
    if (gw < 64 * 128 * 2 * 4) {
        int ks = gw & 3, sp = (gw >> 2) & 1, blk = (gw >> 3) & 127, bh = gw >> 10;
        int r0 = blk * 16 + (lane >> 2);
        int kb = ks * 16 + (lane & 3) * 2;
        const float* qb = q + ((size_t)bh * Sc) * Dc;
        float2 p00 = *(const float2*)(qb + (size_t)r0 * Dc + kb);
        float2 p10 = *(const float2*)(qb + (size_t)(r0 + 8) * Dc + kb);
        float2 p01 = *(const float2*)(qb + (size_t)r0 * Dc + kb + 8);
        float2 p11 = *(const float2*)(qb + (size_t)(r0 + 8) * Dc + kb + 8);
        uint4 o;
        o.x = pk_split(p00.x * 8.f, p00.y * 8.f, sp);
        o.y = pk_split(p10.x * 8.f, p10.y * 8.f, sp);
        o.z = pk_split(p01.x * 8.f, p01.y * 8.f, sp);
        o.w = pk_split(p11.x * 8.f, p11.y * 8.f, sp);
        g_qfrag[(size_t)gw * 32 + lane] = o;
    } else {
        int w2 = gw - 64 * 128 * 2 * 4;
        int kp = w2 & 1, sp = (w2 >> 1) & 1, cbg = (w2 >> 2) & 255, bh = w2 >> 10;
        int n = cbg * 8 + (lane >> 2);
        const float* kr = k + ((size_t)bh * Sc + n) * Dc;
        uint4 o;
        int k0 = (kp * 2) * 16 + (lane & 3) * 2;
        o.x = pk_split(kr[k0], kr[k0 + 1], sp);
        o.y = pk_split(kr[k0 + 8], kr[k0 + 9], sp);
        int k1 = (kp * 2 + 1) * 16 + (lane & 3) * 2;
        o.z = pk_split(kr[k1], kr[k1 + 1], sp);
        o.w = pk_split(kr[k1 + 8], kr[k1 + 9], sp);
        g_kfrag[(size_t)w2 * 32 + lane] = o;
    }
}

// ---------------- main attention kernel: two-pass, barrier-free pass 2 ------
__global__ void __launch_bounds__(256, 2)
attn_main(const float* __restrict__ gv, float* __restrict__ gout)
{
    __shared__ uint4 sKH[1024];          // 16 KB: hi-only K tile (pass 1)
    __shared__ uint4 sAL[8 * 4 * 32];    // 16 KB: A_lo frags per warp
    __shared__ uint32_t sBM[8 * 256];    //  8 KB: per-warp block-max keys

    const int tid = threadIdx.x, w = tid >> 5, lane = tid & 31;
    const uint32_t bh = blockIdx.y;
    const int q0 = blockIdx.x * 128;
    const int blk = blockIdx.x * 8 + w;
    const uint4* kfb = g_kfrag + (size_t)bh * 32768;   // 256 cbg * 128 uint4

    // A_hi resident in regs; A_lo staged to smem (warp-private)
    uint4 AH[4];
    {
        const uint4* qf = g_qfrag + ((size_t)(bh * 128 + blk) * 2) * 4 * 32;
#pragma unroll
        for (int ks = 0; ks < 4; ++ks) AH[ks] = qf[ks * 32 + lane];
#pragma unroll
        for (int ks = 0; ks < 4; ++ks)
            sAL[(w * 4 + ks) * 32 + lane] = qf[(4 + ks) * 32 + lane];
    }

    // ================= PASS 1: hi-only row maxima + block-max cache ========
    float mx0 = -1e30f, mx1 = -1e30f;
    for (int kt = 0; kt < 16; ++kt) {
        __syncthreads();
#pragma unroll
        for (int i = 0; i < 4; ++i) {
            int li = tid + i * 256;
            sKH[li] = kfb[kt * 2048 + ((li >> 6) * 128) + (li & 63)];
        }
        __syncthreads();

#pragma unroll 2
        for (int cb = 0; cb < 16; ++cb) {
            uint4 Bh0 = sKH[cb * 64 + lane];
            uint4 Bh1 = sKH[cb * 64 + 32 + lane];
            float h0 = 0.f, h1 = 0.f, h2 = 0.f, h3 = 0.f;
            mma16816(h0, h1, h2, h3, AH[0].x, AH[0].y, AH[0].z, AH[0].w, Bh0.x, Bh0.y);
            mma16816(h0, h1, h2, h3, AH[1].x, AH[1].y, AH[1].z, AH[1].w, Bh0.z, Bh0.w);
            mma16816(h0, h1, h2, h3, AH[2].x, AH[2].y, AH[2].z, AH[2].w, Bh1.x, Bh1.y);
            mma16816(h0, h1, h2, h3, AH[3].x, AH[3].y, AH[3].z, AH[3].w, Bh1.z, Bh1.w);
            float t0 = fmaxf(h0, h1), t1 = fmaxf(h2, h3);
            mx0 = fmaxf(mx0, t0);
            mx1 = fmaxf(mx1, t1);
            uint32_t key = __reduce_max_sync(0xffffffffu, okey(fmaxf(t0, t1)));
            if (lane == 0) sBM[w * 256 + kt * 16 + cb] = key;
        }
    }

    // finalize per-row maxima (fixed exp bases) + warp-level gate key
    mx0 = fmaxf(mx0, __shfl_xor_sync(0xffffffffu, mx0, 1));
    mx0 = fmaxf(mx0, __shfl_xor_sync(0xffffffffu, mx0, 2));
    mx1 = fmaxf(mx1, __shfl_xor_sync(0xffffffffu, mx1, 1));
    mx1 = fmaxf(mx1, __shfl_xor_sync(0xffffffffu, mx1, 2));
    const float m0 = mx0, m1 = mx1;
    float mmin = fminf(m0, m1);
    mmin = fminf(mmin, __shfl_xor_sync(0xffffffffu, mmin, 4));
    mmin = fminf(mmin, __shfl_xor_sync(0xffffffffu, mmin, 8));
    mmin = fminf(mmin, __shfl_xor_sync(0xffffffffu, mmin, 16));
    const uint32_t gatekey = okey(mmin - 29.0f);
    __syncwarp();   // sBM visibility within warp

    // ========= PASS 2: barrier-free; entered blocks stream from L2 =========
    float O[2][16];
#pragma unroll
    for (int r = 0; r < 2; ++r)
#pragma unroll
        for (int c = 0; c < 16; ++c) O[r][c] = 0.f;
    float l0 = 0.f, l1 = 0.f;

    const uint32_t gq0 = (uint32_t)(q0 + w * 16 + (lane >> 2));
    const float* vb = gv + (size_t)bh * Sc * Dc;

    for (int kt = 0; kt < 16; ++kt) {
        uint32_t mykey = (lane < 16) ? sBM[w * 256 + kt * 16 + lane] : 0u;
        unsigned bmask = __ballot_sync(0xffffffffu, (lane < 16) && (mykey > gatekey));

        while (bmask) {
            const int cb = __ffs(bmask) - 1;
            bmask &= bmask - 1;

            const uint4* kb = kfb + (size_t)(kt * 16 + cb) * 128;
            uint4 Bh0 = kb[lane];
            uint4 Bh1 = kb[32 + lane];
            uint4 Bl0 = kb[64 + lane];
            uint4 Bl1 = kb[96 + lane];

            // dual chain: h = QhKh, x = QlKh + QhKl
            float h0 = 0.f, h1 = 0.f, h2 = 0.f, h3 = 0.f;
            float x0 = 0.f, x1 = 0.f, x2 = 0.f, x3 = 0.f;
#pragma unroll
            for (int ks = 0; ks < 4; ++ks) {
                uint4 AL = sAL[(w * 4 + ks) * 32 + lane];
                uint32_t hb0 = (ks & 1) ? ((ks >> 1) ? Bh1.z : Bh0.z)
                                        : ((ks >> 1) ? Bh1.x : Bh0.x);
                uint32_t hb1 = (ks & 1) ? ((ks >> 1) ? Bh1.w : Bh0.w)
                                        : ((ks >> 1) ? Bh1.y : Bh0.y);
                uint32_t lb0 = (ks & 1) ? ((ks >> 1) ? Bl1.z : Bl0.z)
                                        : ((ks >> 1) ? Bl1.x : Bl0.x);
                uint32_t lb1 = (ks & 1) ? ((ks >> 1) ? Bl1.w : Bl0.w)
                                        : ((ks >> 1) ? Bl1.y : Bl0.y);
                mma16816(x0, x1, x2, x3, AL.x, AL.y, AL.z, AL.w, hb0, hb1);
                mma16816(h0, h1, h2, h3, AH[ks].x, AH[ks].y, AH[ks].z, AH[ks].w, hb0, hb1);
                mma16816(x0, x1, x2, x3, AH[ks].x, AH[ks].y, AH[ks].z, AH[ks].w, lb0, lb1);
            }
            float c0 = h0 + x0, c1 = h1 + x1, c2 = h2 + x2, c3 = h3 + x3;

            // fixed-base softmax contributions
            float e0 = (c0 > m0 - 28.f) ? __expf(c0 - m0) : 0.f;
            float e1 = (c1 > m0 - 28.f) ? __expf(c1 - m0) : 0.f;
            float e2 = (c2 > m1 - 28.f) ? __expf(c2 - m1) : 0.f;
            float e3 = (c3 > m1 - 28.f) ? __expf(c3 - m1) : 0.f;
            l0 += e0 + e1;
            l1 += e2 + e3;

            const int gk0 = kt * 128 + cb * 8 + (lane & 3) * 2;
            bool sv[4] = {false, false, false, false};
            float p10[4] = {0.f, 0.f, 0.f, 0.f};
            if (e0 > 0.f && keep_mask(bh, gq0, gk0))         { sv[0] = true; p10[0] = e0 * 10.f; }
            if (e1 > 0.f && keep_mask(bh, gq0, gk0 + 1))     { sv[1] = true; p10[1] = e1 * 10.f; }
            if (e2 > 0.f && keep_mask(bh, gq0 + 8, gk0))     { sv[2] = true; p10[2] = e2 * 10.f; }
            if (e3 > 0.f && keep_mask(bh, gq0 + 8, gk0 + 1)) { sv[3] = true; p10[3] = e3 * 10.f; }

            if (__ballot_sync(0xffffffffu, sv[0] | sv[1] | sv[2] | sv[3])) {
#pragma unroll
                for (int pos = 0; pos < 4; ++pos) {
                    unsigned mk = __ballot_sync(0xffffffffu, sv[pos]);
                    while (mk) {
                        int src = __ffs(mk) - 1;
                        mk &= mk - 1;
                        int gkb  = __shfl_sync(0xffffffffu, gk0 + (pos & 1), src);
                        float pb = __shfl_sync(0xffffffffu, p10[pos], src);
                        if ((lane >> 2) == (src >> 2)) {
                            const float* vc = vb + (size_t)gkb * Dc + (lane & 3) * 16;
                            float* Or = O[pos >> 1];
#pragma unroll
                            for (int c = 0; c < 4; ++c) {
                                float4 vv = *(const float4*)(vc + 4 * c);
                                Or[4 * c + 0] = fmaf(pb, vv.x, Or[4 * c + 0]);
                                Or[4 * c + 1] = fmaf(pb, vv.y, Or[4 * c + 1]);
                                Or[4 * c + 2] = fmaf(pb, vv.z, Or[4 * c + 2]);
                                Or[4 * c + 3] = fmaf(pb, vv.w, Or[4 * c + 3]);
                            }
                        }
                    }
                }
            }
        }
    }

    // ---- epilogue: quad-sum l, normalize, store ----
    l0 += __shfl_xor_sync(0xffffffffu, l0, 1);
    l0 += __shfl_xor_sync(0xffffffffu, l0, 2);
    l1 += __shfl_xor_sync(0xffffffffu, l1, 1);
    l1 += __shfl_xor_sync(0xffffffffu, l1, 2);
    float il0 = 1.0f / l0, il1 = 1.0f / l1;

    const int gr0 = q0 + w * 16 + (lane >> 2);
    float* o0 = gout + ((size_t)bh * Sc + gr0) * Dc + (lane & 3) * 16;
    float* o1 = gout + ((size_t)bh * Sc + gr0 + 8) * Dc + (lane & 3) * 16;
#pragma unroll
    for (int c = 0; c < 4; ++c) {
        *(float4*)(o0 + 4 * c) = make_float4(O[0][4*c] * il0, O[0][4*c+1] * il0,
                                             O[0][4*c+2] * il0, O[0][4*c+3] * il0);
        *(float4*)(o1 + 4 * c) = make_float4(O[1][4*c] * il1, O[1][4*c+1] * il1,
                                             O[1][4*c+2] * il1, O[1][4*c+3] * il1);
    }
}

extern "C" void kernel_launch(void* const* d_in, const int* in_sizes, int n_in,
                              void* d_out, int out_size)
{
    (void)in_sizes; (void)n_in; (void)out_size;
    const float* q = (const float*)d_in[0];
    const float* k = (const float*)d_in[1];
    const float* v = (const float*)d_in[2];
    float* o = (float*)d_out;

    prepass_kernel<<<16384, 256>>>(q, k);
    dim3 grid(Sc / 128, 64);
    attn_main<<<grid, 256>>>(v, o);
}

// round 15
// speedup vs baseline: 1.3721x; 1.3721x over previous
#include <cuda_runtime.h>
#include <cuda_bf16.h>
#include <cstdint>

static constexpr int Sc = 2048, Dc = 64;

// fragment buffers:
// Q: ((bh*128+blk)*2+sp)*4+ks -> [lane] uint4(a0,a1,a2,a3)
// K: ((bh*256+cbg)*2+sp)*2+kp -> [lane] uint4(ks_even b0,b1, ks_odd b0,b1)
__device__ uint4 g_qfrag[64 * 128 * 2 * 4 * 32];
__device__ uint4 g_kfrag[64 * 256 * 2 * 2 * 32];

__device__ __forceinline__ void threefry2x32(uint32_t c0, uint32_t c1,
                                             uint32_t& o0, uint32_t& o1)
{
    const uint32_t K0 = 0u, K1 = 42u, K2 = 0x1BD11BDAu ^ K0 ^ K1;
    uint32_t x0 = c0 + K0, x1 = c1 + K1;
#define TF_R(r) { x0 += x1; x1 = __funnelshift_l(x1, x1, (r)); x1 ^= x0; }
    TF_R(13) TF_R(15) TF_R(26) TF_R(6)  x0 += K1; x1 += K2 + 1u;
    TF_R(17) TF_R(29) TF_R(16) TF_R(24) x0 += K2; x1 += K0 + 2u;
    TF_R(13) TF_R(15) TF_R(26) TF_R(6)  x0 += K0; x1 += K1 + 3u;
    TF_R(17) TF_R(29) TF_R(16) TF_R(24) x0 += K1; x1 += K2 + 4u;
    TF_R(13) TF_R(15) TF_R(26) TF_R(6)  x0 += K2; x1 += K0 + 5u;
#undef TF_R
    o0 = x0; o1 = x1;
}
__device__ __forceinline__ bool keep_mask(uint32_t bh, uint32_t gq, uint32_t gk)
{
    uint32_t i = (bh << 22) | (gq << 11) | gk, b0, b1;
    threefry2x32(0u, i, b0, b1);
    return ((b0 ^ b1) >> 9) < 838861u;
}

__device__ __forceinline__ uint32_t pk_bf16(float lo, float hi)
{ uint32_t r; asm("cvt.rn.bf16x2.f32 %0, %1, %2;" : "=r"(r) : "f"(hi), "f"(lo)); return r; }

__device__ __forceinline__ uint32_t pk_split(float x, float y, int sp)
{
    float xh = __bfloat162float(__float2bfloat16(x));
    float yh = __bfloat162float(__float2bfloat16(y));
    return sp ? pk_bf16(x - xh, y - yh) : pk_bf16(xh, yh);
}

__device__ __forceinline__ void mma16816(float& c0, float& c1, float& c2, float& c3,
                                         uint32_t a0, uint32_t a1, uint32_t a2, uint32_t a3,
                                         uint32_t b0, uint32_t b1)
{
    asm volatile("mma.sync.aligned.m16n8k16.row.col.f32.bf16.bf16.f32 "
                 "{%0,%1,%2,%3}, {%4,%5,%6,%7}, {%8,%9}, {%0,%1,%2,%3};"
                 : "+f"(c0), "+f"(c1), "+f"(c2), "+f"(c3)
                 : "r"(a0), "r"(a1), "r"(a2), "r"(a3), "r"(b0), "r"(b1));
}

// ---------------- pre-pass (unchanged) ---------------------------------------
__global__ void __launch_bounds__(256)
prepass_kernel(const float* __restrict__ q, const float* __restrict__ k)
{
    int gw = (blockIdx.x * 256 + threadIdx.x) >> 5;
    int lane = threadIdx.x & 31;
    if (gw < 64 * 128 * 2 * 4) {
        int ks = gw & 3, sp = (gw >> 2) & 1, blk = (gw >> 3) & 127, bh = gw >> 10;
        int r0 = blk * 16 + (lane >> 2);
        int kb = ks * 16 + (lane & 3) * 2;
        const float* qb = q + ((size_t)bh * Sc) * Dc;
        float2 p00 = *(const float2*)(qb + (size_t)r0 * Dc + kb);
        float2 p10 = *(const float2*)(qb + (size_t)(r0 + 8) * Dc + kb);
        float2 p01 = *(const float2*)(qb + (size_t)r0 * Dc + kb + 8);
        float2 p11 = *(const float2*)(qb + (size_t)(r0 + 8) * Dc + kb + 8);
        uint4 o;
        o.x = pk_split(p00.x * 8.f, p00.y * 8.f, sp);
        o.y = pk_split(p10.x * 8.f, p10.y * 8.f, sp);
        o.z = pk_split(p01.x * 8.f, p01.y * 8.f, sp);
        o.w = pk_split(p11.x * 8.f, p11.y * 8.f, sp);
        g_qfrag[(size_t)gw * 32 + lane] = o;
    } else {
        int w2 = gw - 64 * 128 * 2 * 4;
        int kp = w2 & 1, sp = (w2 >> 1) & 1, cbg = (w2 >> 2) & 255, bh = w2 >> 10;
        int n = cbg * 8 + (lane >> 2);
        const float* kr = k + ((size_t)bh * Sc + n) * Dc;
        uint4 o;
        int k0 = (kp * 2) * 16 + (lane & 3) * 2;
        o.x = pk_split(kr[k0], kr[k0 + 1], sp);
        o.y = pk_split(kr[k0 + 8], kr[k0 + 9], sp);
        int k1 = (kp * 2 + 1) * 16 + (lane & 3) * 2;
        o.z = pk_split(kr[k1], kr[k1 + 1], sp);
        o.w = pk_split(kr[k1 + 8], kr[k1 + 9], sp);
        g_kfrag[(size_t)w2 * 32 + lane] = o;
    }
}

// ---------------- main attention kernel: per-row quantized gating -----------
// dynamic smem layout (bytes):
//   sKH : [0, 16384)        hi-only K tile (pass 1)
//   sAL : [16384, 32768)    A_lo frags per warp
//   sRB : [32768, 65536)    per-warp per-block per-row u8 maxima [w][256][16]
//   sTH : [65536, 65664)    per-warp per-row u8 thresholds [w][16]
static constexpr int SMEM_BYTES = 65664;

__global__ void __launch_bounds__(256, 2)
attn_main(const float* __restrict__ gv, float* __restrict__ gout)
{
    extern __shared__ uint8_t dynsm[];
    uint4*    sKH = (uint4*)dynsm;
    uint4*    sAL = (uint4*)(dynsm + 16384);
    uint8_t*  sRB = dynsm + 32768;
    uint8_t*  sTH = dynsm + 65536;

    const int tid = threadIdx.x, w = tid >> 5, lane = tid & 31;
    const uint32_t bh = blockIdx.y;
    const int q0 = blockIdx.x * 128;
    const int blk = blockIdx.x * 8 + w;
    const uint4* kfb = g_kfrag + (size_t)bh * 32768;   // 256 cbg * 128 uint4

    // A_hi resident in regs; A_lo staged to smem (warp-private)
    uint4 AH[4];
    {
        const uint4* qf = g_qfrag + ((size_t)(bh * 128 + blk) * 2) * 4 * 32;
#pragma unroll
        for (int ks = 0; ks < 4; ++ks) AH[ks] = qf[ks * 32 + lane];
#pragma unroll
        for (int ks = 0; ks < 4; ++ks)
            sAL[(w * 4 + ks) * 32 + lane] = qf[(4 + ks) * 32 + lane];
    }

    // ===== PASS 1: hi-only row maxima + per-row quantized block maxima ======
    float mx0 = -1e30f, mx1 = -1e30f;
    for (int kt = 0; kt < 16; ++kt) {
        __syncthreads();
#pragma unroll
        for (int i = 0; i < 4; ++i) {
            int li = tid + i * 256;
            sKH[li] = kfb[kt * 2048 + ((li >> 6) * 128) + (li & 63)];
        }
        __syncthreads();

#pragma unroll 2
        for (int cb = 0; cb < 16; ++cb) {
            uint4 Bh0 = sKH[cb * 64 + lane];
            uint4 Bh1 = sKH[cb * 64 + 32 + lane];
            float h0 = 0.f, h1 = 0.f, h2 = 0.f, h3 = 0.f;
            mma16816(h0, h1, h2, h3, AH[0].x, AH[0].y, AH[0].z, AH[0].w, Bh0.x, Bh0.y);
            mma16816(h0, h1, h2, h3, AH[1].x, AH[1].y, AH[1].z, AH[1].w, Bh0.z, Bh0.w);
            mma16816(h0, h1, h2, h3, AH[2].x, AH[2].y, AH[2].z, AH[2].w, Bh1.x, Bh1.y);
            mma16816(h0, h1, h2, h3, AH[3].x, AH[3].y, AH[3].z, AH[3].w, Bh1.z, Bh1.w);
            float t0 = fmaxf(h0, h1), t1 = fmaxf(h2, h3);
            mx0 = fmaxf(mx0, t0);
            mx1 = fmaxf(mx1, t1);
            // quad-reduce: per-row block maxima (rows r and r+8)
            t0 = fmaxf(t0, __shfl_xor_sync(0xffffffffu, t0, 1));
            t0 = fmaxf(t0, __shfl_xor_sync(0xffffffffu, t0, 2));
            t1 = fmaxf(t1, __shfl_xor_sync(0xffffffffu, t1, 1));
            t1 = fmaxf(t1, __shfl_xor_sync(0xffffffffu, t1, 2));
            if ((lane & 3) == 0) {
                int r = lane >> 2;
                int base = (w * 256 + kt * 16 + cb) * 16;
                int b0 = min(max((int)ceilf(t0) - 100, 0), 255);
                int b1 = min(max((int)ceilf(t1) - 100, 0), 255);
                sRB[base + r] = (uint8_t)b0;
                sRB[base + r + 8] = (uint8_t)b1;
            }
        }
    }

    // finalize per-row maxima (fixed exp bases) + per-row threshold bytes
    mx0 = fmaxf(mx0, __shfl_xor_sync(0xffffffffu, mx0, 1));
    mx0 = fmaxf(mx0, __shfl_xor_sync(0xffffffffu, mx0, 2));
    mx1 = fmaxf(mx1, __shfl_xor_sync(0xffffffffu, mx1, 1));
    mx1 = fmaxf(mx1, __shfl_xor_sync(0xffffffffu, mx1, 2));
    const float m0 = mx0, m1 = mx1;
    if ((lane & 3) == 0) {
        int r = lane >> 2;
        int t0 = min(max((int)floorf(m0 - 31.f) - 100, 0), 255);
        int t1 = min(max((int)floorf(m1 - 31.f) - 100, 0), 255);
        sTH[w * 16 + r] = (uint8_t)t0;
        sTH[w * 16 + r + 8] = (uint8_t)t1;
    }
    __syncwarp();
    // each lane caches the 8 thresholds for its gating half (rows half*8..+7)
    const uint2 thv = *(const uint2*)&sTH[w * 16 + (lane >> 4) * 8];
    const int cb_l = lane & 15;

    // ===== PASS 2: per-row-gated; entered blocks stream from L2 =============
    float O[2][16];
#pragma unroll
    for (int r = 0; r < 2; ++r)
#pragma unroll
        for (int c = 0; c < 16; ++c) O[r][c] = 0.f;
    float l0 = 0.f, l1 = 0.f;

    const uint32_t gq0 = (uint32_t)(q0 + w * 16 + (lane >> 2));
    const float* vb = gv + (size_t)bh * Sc * Dc;

    for (int kt = 0; kt < 16; ++kt) {
        // union-of-rows gate: lane tests 8 rows of one block via SIMD bytes
        const uint8_t* rbp = &sRB[(w * 256 + kt * 16 + cb_l) * 16 + (lane >> 4) * 8];
        uint2 rbv = *(const uint2*)rbp;
        unsigned ge = __vsetgeu4(rbv.x, thv.x) | __vsetgeu4(rbv.y, thv.y);
        unsigned bal = __ballot_sync(0xffffffffu, ge != 0u);
        unsigned bmask = (bal & 0xffffu) | (bal >> 16);

        while (bmask) {
            const int cb = __ffs(bmask) - 1;
            bmask &= bmask - 1;

            const uint4* kb = kfb + (size_t)(kt * 16 + cb) * 128;
            uint4 Bh0 = kb[lane];
            uint4 Bh1 = kb[32 + lane];
            uint4 Bl0 = kb[64 + lane];
            uint4 Bl1 = kb[96 + lane];

            // dual chain: h = QhKh, x = QlKh + QhKl
            float h0 = 0.f, h1 = 0.f, h2 = 0.f, h3 = 0.f;
            float x0 = 0.f, x1 = 0.f, x2 = 0.f, x3 = 0.f;
#pragma unroll
            for (int ks = 0; ks < 4; ++ks) {
                uint4 AL = sAL[(w * 4 + ks) * 32 + lane];
                uint32_t hb0 = (ks & 1) ? ((ks >> 1) ? Bh1.z : Bh0.z)
                                        : ((ks >> 1) ? Bh1.x : Bh0.x);
                uint32_t hb1 = (ks & 1) ? ((ks >> 1) ? Bh1.w : Bh0.w)
                                        : ((ks >> 1) ? Bh1.y : Bh0.y);
                uint32_t lb0 = (ks & 1) ? ((ks >> 1) ? Bl1.z : Bl0.z)
                                        : ((ks >> 1) ? Bl1.x : Bl0.x);
                uint32_t lb1 = (ks & 1) ? ((ks >> 1) ? Bl1.w : Bl0.w)
                                        : ((ks >> 1) ? Bl1.y : Bl0.y);
                mma16816(x0, x1, x2, x3, AL.x, AL.y, AL.z, AL.w, hb0, hb1);
                mma16816(h0, h1, h2, h3, AH[ks].x, AH[ks].y, AH[ks].z, AH[ks].w, hb0, hb1);
                mma16816(x0, x1, x2, x3, AH[ks].x, AH[ks].y, AH[ks].z, AH[ks].w, lb0, lb1);
            }
            float c0 = h0 + x0, c1 = h1 + x1, c2 = h2 + x2, c3 = h3 + x3;

            // fixed-base softmax contributions
            float e0 = (c0 > m0 - 28.f) ? __expf(c0 - m0) : 0.f;
            float e1 = (c1 > m0 - 28.f) ? __expf(c1 - m0) : 0.f;
            float e2 = (c2 > m1 - 28.f) ? __expf(c2 - m1) : 0.f;
            float e3 = (c3 > m1 - 28.f) ? __expf(c3 - m1) : 0.f;
            l0 += e0 + e1;
            l1 += e2 + e3;

            const int gk0 = kt * 128 + cb * 8 + (lane & 3) * 2;
            bool sv[4] = {false, false, false, false};
            float p10[4] = {0.f, 0.f, 0.f, 0.f};
            if (e0 > 0.f && keep_mask(bh, gq0, gk0))         { sv[0] = true; p10[0] = e0 * 10.f; }
            if (e1 > 0.f && keep_mask(bh, gq0, gk0 + 1))     { sv[1] = true; p10[1] = e1 * 10.f; }
            if (e2 > 0.f && keep_mask(bh, gq0 + 8, gk0))     { sv[2] = true; p10[2] = e2 * 10.f; }
            if (e3 > 0.f && keep_mask(bh, gq0 + 8, gk0 + 1)) { sv[3] = true; p10[3] = e3 * 10.f; }

            if (__ballot_sync(0xffffffffu, sv[0] | sv[1] | sv[2] | sv[3])) {
#pragma unroll
                for (int pos = 0; pos < 4; ++pos) {
                    unsigned mk = __ballot_sync(0xffffffffu, sv[pos]);
                    while (mk) {
                        int src = __ffs(mk) - 1;
                        mk &= mk - 1;
                        int gkb  = __shfl_sync(0xffffffffu, gk0 + (pos & 1), src);
                        float pb = __shfl_sync(0xffffffffu, p10[pos], src);
                        if ((lane >> 2) == (src >> 2)) {
                            const float* vc = vb + (size_t)gkb * Dc + (lane & 3) * 16;
                            float* Or = O[pos >> 1];
#pragma unroll
                            for (int c = 0; c < 4; ++c) {
                                float4 vv = *(const float4*)(vc + 4 * c);
                                Or[4 * c + 0] = fmaf(pb, vv.x, Or[4 * c + 0]);
                                Or[4 * c + 1] = fmaf(pb, vv.y, Or[4 * c + 1]);
                                Or[4 * c + 2] = fmaf(pb, vv.z, Or[4 * c + 2]);
                                Or[4 * c + 3] = fmaf(pb, vv.w, Or[4 * c + 3]);
                            }
                        }
                    }
                }
            }
        }
    }

    // ---- epilogue: quad-sum l, normalize, store ----
    l0 += __shfl_xor_sync(0xffffffffu, l0, 1);
    l0 += __shfl_xor_sync(0xffffffffu, l0, 2);
    l1 += __shfl_xor_sync(0xffffffffu, l1, 1);
    l1 += __shfl_xor_sync(0xffffffffu, l1, 2);
    float il0 = 1.0f / l0, il1 = 1.0f / l1;

    const int gr0 = q0 + w * 16 + (lane >> 2);
    float* o0 = gout + ((size_t)bh * Sc + gr0) * Dc + (lane & 3) * 16;
    float* o1 = gout + ((size_t)bh * Sc + gr0 + 8) * Dc + (lane & 3) * 16;
#pragma unroll
    for (int c = 0; c < 4; ++c) {
        *(float4*)(o0 + 4 * c) = make_float4(O[0][4*c] * il0, O[0][4*c+1] * il0,
                                             O[0][4*c+2] * il0, O[0][4*c+3] * il0);
        *(float4*)(o1 + 4 * c) = make_float4(O[1][4*c] * il1, O[1][4*c+1] * il1,
                                             O[1][4*c+2] * il1, O[1][4*c+3] * il1);
    }
}

extern "C" void kernel_launch(void* const* d_in, const int* in_sizes, int n_in,
                              void* d_out, int out_size)
{
    (void)in_sizes; (void)n_in; (void)out_size;
    const float* q = (const float*)d_in[0];
    const float* k = (const float*)d_in[1];
    const float* v = (const float*)d_in[2];
    float* o = (float*)d_out;

    prepass_kernel<<<16384, 256>>>(q, k);

    cudaFuncSetAttribute(attn_main,
                         cudaFuncAttributeMaxDynamicSharedMemorySize, SMEM_BYTES);
    dim3 grid(Sc / 128, 64);
    attn_main<<<grid, 256, SMEM_BYTES>>>(v, o);
}